// round 6
// baseline (speedup 1.0000x reference)
#include <cuda_runtime.h>

#define NN 100000
#define NE 1600000

typedef unsigned long long u64;

// ---------------- scratch (static device globals; no allocs) ----------------
__device__ int   g_cnt[NN];
__device__ int   g_off[NN + 1];
__device__ int   g_pos[NN];
__device__ int   g_srcs[NE];
__device__ float g_B0[256 * 128];              // rows 0..127 = W_l0, rows 128..255 = W_r0
__device__ float g_B1[128 * 128];              // [W_l1 | W_r1], row-major K=128 x 128
__device__ float g_m0[(size_t)NN * 128];       // mean-aggregated x
__device__ float g_h[(size_t)NN * 128];        // relu'd layer-0 output
__device__ float g_yz1[(size_t)NN * 128];      // h @ B1  (y1 = cols 0..63, z1 = 64..127)

// ---------------- packed f32x2 helpers (sm_103a FFMA2 path) ----------------
__device__ __forceinline__ u64 pack2(float lo, float hi) {
    u64 r;
    asm("mov.b64 %0, {%1, %2};" : "=l"(r) : "r"(__float_as_uint(lo)), "r"(__float_as_uint(hi)));
    return r;
}
__device__ __forceinline__ u64 dup2(float v) {
    u64 r;
    unsigned u = __float_as_uint(v);
    asm("mov.b64 %0, {%1, %1};" : "=l"(r) : "r"(u));
    return r;
}
__device__ __forceinline__ void fma2(u64& d, u64 a, u64 b) {
    asm("fma.rn.f32x2 %0, %1, %2, %3;" : "=l"(d) : "l"(a), "l"(b), "l"(d));
}
__device__ __forceinline__ float2 unpack2(u64 v) {
    unsigned lo, hi;
    asm("mov.b64 {%0, %1}, %2;" : "=r"(lo), "=r"(hi) : "l"(v));
    return make_float2(__uint_as_float(lo), __uint_as_float(hi));
}

// ---------------- CSR build ----------------
__global__ void k_zero() {
    int i = blockIdx.x * blockDim.x + threadIdx.x;
    if (i < NN) g_cnt[i] = 0;
}

// edge_index is int32 (JAX x64 disabled).
__global__ void k_count(const int* __restrict__ ei) {
    int e = blockIdx.x * blockDim.x + threadIdx.x;
    if (e < NE) {
        unsigned d = (unsigned)ei[NE + e];
        if (d < NN) atomicAdd(&g_cnt[d], 1);
    }
}

__global__ void k_scan() {
    __shared__ int sm[1024];
    int tid = threadIdx.x;
    const int CH = (NN + 1023) / 1024;
    int start = tid * CH;
    int end = min(start + CH, NN);
    int s = 0;
    for (int i = start; i < end; i++) s += g_cnt[i];
    sm[tid] = s;
    __syncthreads();
    for (int d = 1; d < 1024; d <<= 1) {
        int v = (tid >= d) ? sm[tid - d] : 0;
        __syncthreads();
        sm[tid] += v;
        __syncthreads();
    }
    int run = sm[tid] - s;  // exclusive prefix
    for (int i = start; i < end; i++) {
        g_off[i] = run;
        g_pos[i] = run;
        run += g_cnt[i];
    }
    if (tid == 1023) g_off[NN] = run;
}

__global__ void k_scatter(const int* __restrict__ ei) {
    int e = blockIdx.x * blockDim.x + threadIdx.x;
    if (e < NE) {
        unsigned d = (unsigned)ei[NE + e];
        if (d < NN) {
            int p = atomicAdd(&g_pos[d], 1);
            unsigned s = (unsigned)ei[e];
            g_srcs[p] = (s < NN) ? (int)s : 0;
        }
    }
}

// ---------------- pack weights ----------------
__global__ void k_pack(const float* __restrict__ Wl0, const float* __restrict__ Wr0,
                       const float* __restrict__ Wl1, const float* __restrict__ Wr1) {
    int i = blockIdx.x * blockDim.x + threadIdx.x;
    if (i < 256 * 128) {
        int k = i >> 7, j = i & 127;
        g_B0[i] = (k < 128) ? Wl0[k * 128 + j] : Wr0[(k - 128) * 128 + j];
    }
    if (i < 128 * 128) {
        int k = i >> 7, j = i & 127;
        g_B1[i] = (j < 64) ? Wl1[(k << 6) + j] : Wr1[(k << 6) + (j - 64)];
    }
}

// ---------------- input-space mean aggregation: m0 = mean(x[src]) ----------------
// warp per node; lane handles float4 of the 128-wide row; 2-deep unrolled gather.
__global__ void k_aggx(const float* __restrict__ x) {
    int node = blockIdx.x * 8 + (threadIdx.x >> 5);
    int lane = threadIdx.x & 31;
    if (node >= NN) return;
    int beg = g_off[node], end = g_off[node + 1];
    float inv = 1.0f / (float)max(end - beg, 1);
    float4 a0 = make_float4(0.f, 0.f, 0.f, 0.f);
    float4 a1 = make_float4(0.f, 0.f, 0.f, 0.f);
    int e = beg;
    for (; e + 2 <= end; e += 2) {
        int s0 = g_srcs[e], s1 = g_srcs[e + 1];
        float4 v0 = *(const float4*)&x[(size_t)s0 * 128 + lane * 4];
        float4 v1 = *(const float4*)&x[(size_t)s1 * 128 + lane * 4];
        a0.x += v0.x; a0.y += v0.y; a0.z += v0.z; a0.w += v0.w;
        a1.x += v1.x; a1.y += v1.y; a1.z += v1.z; a1.w += v1.w;
    }
    if (e < end) {
        int s0 = g_srcs[e];
        float4 v0 = *(const float4*)&x[(size_t)s0 * 128 + lane * 4];
        a0.x += v0.x; a0.y += v0.y; a0.z += v0.z; a0.w += v0.w;
    }
    float4 r;
    r.x = (a0.x + a1.x) * inv;
    r.y = (a0.y + a1.y) * inv;
    r.z = (a0.z + a1.z) * inv;
    r.w = (a0.w + a1.w) * inv;
    *(float4*)&g_m0[(size_t)node * 128 + lane * 4] = r;
}

// ---------------- GEMM0: h = relu(m0 @ Wl0 + x @ Wr0 + b)  [K=256 concat] ----------------
// BM=128, BN=128 (full width), BK=8, 256 threads, 8x8 per thread, FFMA2.
__global__ __launch_bounds__(256, 2) void k_gemm0(const float* __restrict__ x,
                                                  const float* __restrict__ bias) {
    __shared__ float As[8][132];
    __shared__ float Bs[8][132];

    int tid = threadIdx.x;
    int m0b = blockIdx.x * 128;
    int tx = tid & 15, ty = tid >> 4;

    int aRow = tid >> 1;
    int aK = (tid & 1) * 4;
    int bRow = tid >> 5;
    int bCol = (tid & 31) * 4;

    u64 acc[8][4];
#pragma unroll
    for (int i = 0; i < 8; i++)
#pragma unroll
        for (int j = 0; j < 4; j++) acc[i][j] = 0ull;

    for (int k0 = 0; k0 < 256; k0 += 8) {
        const float* __restrict__ A = (k0 < 128) ? g_m0 : x;
        int kk = k0 & 127;
        float4 av = make_float4(0.f, 0.f, 0.f, 0.f);
        if (m0b + aRow < NN) av = *(const float4*)&A[(size_t)(m0b + aRow) * 128 + kk + aK];
        As[aK + 0][aRow] = av.x;
        As[aK + 1][aRow] = av.y;
        As[aK + 2][aRow] = av.z;
        As[aK + 3][aRow] = av.w;
        *(float4*)&Bs[bRow][bCol] = *(const float4*)&g_B0[(size_t)(k0 + bRow) * 128 + bCol];
        __syncthreads();

#pragma unroll
        for (int k = 0; k < 8; k++) {
            float4 b0 = *(const float4*)&Bs[k][tx * 4];
            float4 b1 = *(const float4*)&Bs[k][tx * 4 + 64];
            float4 a0v = *(const float4*)&As[k][ty * 4];
            float4 a1v = *(const float4*)&As[k][ty * 4 + 64];
            u64 bp[4] = {pack2(b0.x, b0.y), pack2(b0.z, b0.w),
                         pack2(b1.x, b1.y), pack2(b1.z, b1.w)};
            float ar[8] = {a0v.x, a0v.y, a0v.z, a0v.w, a1v.x, a1v.y, a1v.z, a1v.w};
#pragma unroll
            for (int i = 0; i < 8; i++) {
                u64 ad = dup2(ar[i]);
#pragma unroll
                for (int j = 0; j < 4; j++) fma2(acc[i][j], ad, bp[j]);
            }
        }
        __syncthreads();
    }

#pragma unroll
    for (int i = 0; i < 8; i++) {
        int row = m0b + ty * 4 + (i & 3) + (i >> 2) * 64;
        if (row < NN) {
#pragma unroll
            for (int g = 0; g < 2; g++) {
                int col = tx * 4 + g * 64;
                float2 lo = unpack2(acc[i][g * 2 + 0]);
                float2 hi = unpack2(acc[i][g * 2 + 1]);
                float4 bb = *(const float4*)&bias[col];
                float4 v;
                v.x = fmaxf(lo.x + bb.x, 0.f);
                v.y = fmaxf(lo.y + bb.y, 0.f);
                v.z = fmaxf(hi.x + bb.z, 0.f);
                v.w = fmaxf(hi.y + bb.w, 0.f);
                *(float4*)&g_h[(size_t)row * 128 + col] = v;
            }
        }
    }
}

// ---------------- GEMM1: yz1 = h @ [W_l1 | W_r1]  (K=128, NB=128) ----------------
__global__ __launch_bounds__(256, 2) void k_gemm1() {
    __shared__ float As[8][132];
    __shared__ float Bs[8][132];

    int tid = threadIdx.x;
    int m0b = blockIdx.x * 128;
    int tx = tid & 15, ty = tid >> 4;

    int aRow = tid >> 1;
    int aK = (tid & 1) * 4;
    int bRow = tid >> 5;
    int bCol = (tid & 31) * 4;

    u64 acc[8][4];
#pragma unroll
    for (int i = 0; i < 8; i++)
#pragma unroll
        for (int j = 0; j < 4; j++) acc[i][j] = 0ull;

    for (int k0 = 0; k0 < 128; k0 += 8) {
        float4 av = make_float4(0.f, 0.f, 0.f, 0.f);
        if (m0b + aRow < NN) av = *(const float4*)&g_h[(size_t)(m0b + aRow) * 128 + k0 + aK];
        As[aK + 0][aRow] = av.x;
        As[aK + 1][aRow] = av.y;
        As[aK + 2][aRow] = av.z;
        As[aK + 3][aRow] = av.w;
        *(float4*)&Bs[bRow][bCol] = *(const float4*)&g_B1[(size_t)(k0 + bRow) * 128 + bCol];
        __syncthreads();

#pragma unroll
        for (int k = 0; k < 8; k++) {
            float4 b0 = *(const float4*)&Bs[k][tx * 4];
            float4 b1 = *(const float4*)&Bs[k][tx * 4 + 64];
            float4 a0v = *(const float4*)&As[k][ty * 4];
            float4 a1v = *(const float4*)&As[k][ty * 4 + 64];
            u64 bp[4] = {pack2(b0.x, b0.y), pack2(b0.z, b0.w),
                         pack2(b1.x, b1.y), pack2(b1.z, b1.w)};
            float ar[8] = {a0v.x, a0v.y, a0v.z, a0v.w, a1v.x, a1v.y, a1v.z, a1v.w};
#pragma unroll
            for (int i = 0; i < 8; i++) {
                u64 ad = dup2(ar[i]);
#pragma unroll
                for (int j = 0; j < 4; j++) fma2(acc[i][j], ad, bp[j]);
            }
        }
        __syncthreads();
    }

#pragma unroll
    for (int i = 0; i < 8; i++) {
        int row = m0b + ty * 4 + (i & 3) + (i >> 2) * 64;
        if (row < NN) {
#pragma unroll
            for (int g = 0; g < 2; g++) {
                float2 lo = unpack2(acc[i][g * 2 + 0]);
                float2 hi = unpack2(acc[i][g * 2 + 1]);
                float4 v = make_float4(lo.x, lo.y, hi.x, hi.y);
                *(float4*)&g_yz1[(size_t)row * 128 + tx * 4 + g * 64] = v;
            }
        }
    }
}

// ---------------- layer-1 aggregate + bias + root ----------------
__global__ void k_agg2(const float* __restrict__ bias, float* __restrict__ out) {
    int node = blockIdx.x * 8 + (threadIdx.x >> 5);
    int lane = threadIdx.x & 31;
    if (node >= NN) return;
    int beg = g_off[node], end = g_off[node + 1];
    float inv = 1.0f / (float)max(end - beg, 1);
    float2 a0 = make_float2(0.f, 0.f), a1 = make_float2(0.f, 0.f);
    int e = beg;
    for (; e + 2 <= end; e += 2) {
        int s0 = g_srcs[e], s1 = g_srcs[e + 1];
        float2 v0 = *(const float2*)&g_yz1[(size_t)s0 * 128 + lane * 2];
        float2 v1 = *(const float2*)&g_yz1[(size_t)s1 * 128 + lane * 2];
        a0.x += v0.x; a0.y += v0.y;
        a1.x += v1.x; a1.y += v1.y;
    }
    if (e < end) {
        int s0 = g_srcs[e];
        float2 v0 = *(const float2*)&g_yz1[(size_t)s0 * 128 + lane * 2];
        a0.x += v0.x; a0.y += v0.y;
    }
    float2 z = *(const float2*)&g_yz1[(size_t)node * 128 + 64 + lane * 2];
    float2 b = *(const float2*)&bias[lane * 2];
    float2 r;
    r.x = fmaf(a0.x + a1.x, inv, b.x + z.x);
    r.y = fmaf(a0.y + a1.y, inv, b.y + z.y);
    *(float2*)&out[(size_t)node * 64 + lane * 2] = r;
}

// ---------------- launch ----------------
extern "C" void kernel_launch(void* const* d_in, const int* in_sizes, int n_in,
                              void* d_out, int out_size) {
    const float* x = (const float*)d_in[0];
    const int* ei = (const int*)d_in[1];          // int32 edge_index [2, NE]
    const float* Wl0 = (const float*)d_in[2];
    const float* bl0 = (const float*)d_in[3];
    const float* Wr0 = (const float*)d_in[4];
    const float* Wl1 = (const float*)d_in[5];
    const float* bl1 = (const float*)d_in[6];
    const float* Wr1 = (const float*)d_in[7];
    float* out = (float*)d_out;

    // CSR build (every launch; graph-replay safe)
    k_zero<<<(NN + 255) / 256, 256>>>();
    k_count<<<(NE + 255) / 256, 256>>>(ei);
    k_scan<<<1, 1024>>>();
    k_scatter<<<(NE + 255) / 256, 256>>>(ei);
    k_pack<<<(256 * 128 + 255) / 256, 256>>>(Wl0, Wr0, Wl1, Wr1);

    int mt = (NN + 127) / 128;  // 782
    // m0 = mean(x[src])  (gather from L2-resident x)
    k_aggx<<<(NN + 7) / 8, 256>>>(x);
    // h = relu(m0 @ Wl0 + x @ Wr0 + b0)
    k_gemm0<<<mt, 256>>>(x, bl0);
    // yz1 = h @ [W_l1 | W_r1]
    k_gemm1<<<mt, 256>>>();
    // out = mean_agg(y1) + b1 + z1
    k_agg2<<<(NN + 7) / 8, 256>>>(bl1, out);
}

// round 7
// speedup vs baseline: 2.0608x; 2.0608x over previous
#include <cuda_runtime.h>

#define NN 100000
#define NE 1600000
#define NPART 98   // ceil(NN/1024)

// ---------------- scratch (static device globals; no allocs) ----------------
__device__ int   g_cnt[NN];
__device__ int   g_off[NN + 1];
__device__ int   g_pos[NN];
__device__ int   g_part[NPART];
__device__ int   g_srcs[NE];
__device__ float g_B0[256 * 128];              // rows 0..127 = W_l0, rows 128..255 = W_r0
__device__ float g_B1[128 * 128];              // [W_l1 | W_r1], K=128 x 128
__device__ float g_m0[(size_t)NN * 128];       // mean-aggregated x
__device__ float g_h[(size_t)NN * 128];        // relu'd layer-0 output
__device__ float g_yz1[(size_t)NN * 128];      // h @ B1  (y1 = cols 0..63, z1 = 64..127)

// ---------------- tf32 mma helpers ----------------
__device__ __forceinline__ unsigned f2tf32(float f) {
    unsigned r;
    asm("cvt.rna.tf32.f32 %0, %1;" : "=r"(r) : "f"(f));
    return r;
}
__device__ __forceinline__ unsigned sptr(const void* p) {
    return (unsigned)__cvta_generic_to_shared(p);
}
#define LDSM4(R, addr)                                                              \
    asm volatile("ldmatrix.sync.aligned.m8n8.x4.shared.b16 {%0,%1,%2,%3}, [%4];"    \
                 : "=r"((R)[0]), "=r"((R)[1]), "=r"((R)[2]), "=r"((R)[3])           \
                 : "r"(addr))
__device__ __forceinline__ void mma_tf32(float* c, const unsigned* a, unsigned b0, unsigned b1) {
    asm volatile(
        "mma.sync.aligned.m16n8k8.row.col.f32.tf32.tf32.f32 "
        "{%0,%1,%2,%3},{%4,%5,%6,%7},{%8,%9},{%0,%1,%2,%3};"
        : "+f"(c[0]), "+f"(c[1]), "+f"(c[2]), "+f"(c[3])
        : "r"(a[0]), "r"(a[1]), "r"(a[2]), "r"(a[3]), "r"(b0), "r"(b1));
}

// ---------------- CSR build ----------------
__global__ void k_zero() {
    int i = blockIdx.x * blockDim.x + threadIdx.x;
    if (i < NN) g_cnt[i] = 0;
}

// edge_index is int32 (JAX x64 disabled).
__global__ void k_count(const int* __restrict__ ei) {
    int e = blockIdx.x * blockDim.x + threadIdx.x;
    if (e < NE) {
        unsigned d = (unsigned)ei[NE + e];
        if (d < NN) atomicAdd(&g_cnt[d], 1);
    }
}

__global__ void k_scanA() {  // grid NPART, block 1024: block sums
    int i = blockIdx.x * 1024 + threadIdx.x;
    int v = (i < NN) ? g_cnt[i] : 0;
    __shared__ int ws[32];
    int lane = threadIdx.x & 31, w = threadIdx.x >> 5;
#pragma unroll
    for (int d = 16; d; d >>= 1) v += __shfl_down_sync(~0u, v, d);
    if (!lane) ws[w] = v;
    __syncthreads();
    if (!w) {
        int s = ws[lane];
#pragma unroll
        for (int d = 16; d; d >>= 1) s += __shfl_down_sync(~0u, s, d);
        if (!lane) g_part[blockIdx.x] = s;
    }
}

__global__ void k_scanB() {  // 1 block: exclusive scan of partials
    if (threadIdx.x == 0) {
        int run = 0;
        for (int b = 0; b < NPART; b++) {
            int c = g_part[b];
            g_part[b] = run;
            run += c;
        }
        g_off[NN] = run;
    }
}

__global__ void k_scanC() {  // grid NPART, block 1024: local exclusive scan + offset
    int i = blockIdx.x * 1024 + threadIdx.x;
    int c = (i < NN) ? g_cnt[i] : 0;
    int v = c;
    int lane = threadIdx.x & 31, w = threadIdx.x >> 5;
#pragma unroll
    for (int d = 1; d < 32; d <<= 1) {
        int t = __shfl_up_sync(~0u, v, d);
        if (lane >= d) v += t;
    }
    __shared__ int ws[32];
    if (lane == 31) ws[w] = v;
    __syncthreads();
    if (!w) {
        int s = ws[lane];
#pragma unroll
        for (int d = 1; d < 32; d <<= 1) {
            int t = __shfl_up_sync(~0u, s, d);
            if (lane >= d) s += t;
        }
        ws[lane] = s;
    }
    __syncthreads();
    int excl = v - c + (w ? ws[w - 1] : 0) + g_part[blockIdx.x];
    if (i < NN) {
        g_off[i] = excl;
        g_pos[i] = excl;
    }
}

__global__ void k_scatter(const int* __restrict__ ei) {
    int e = blockIdx.x * blockDim.x + threadIdx.x;
    if (e < NE) {
        unsigned d = (unsigned)ei[NE + e];
        if (d < NN) {
            int p = atomicAdd(&g_pos[d], 1);
            unsigned s = (unsigned)ei[e];
            g_srcs[p] = (s < NN) ? (int)s : 0;
        }
    }
}

// ---------------- pack weights ----------------
__global__ void k_pack(const float* __restrict__ Wl0, const float* __restrict__ Wr0,
                       const float* __restrict__ Wl1, const float* __restrict__ Wr1) {
    int i = blockIdx.x * blockDim.x + threadIdx.x;
    if (i < 256 * 128) {
        int k = i >> 7, j = i & 127;
        g_B0[i] = (k < 128) ? Wl0[k * 128 + j] : Wr0[(k - 128) * 128 + j];
    }
    if (i < 128 * 128) {
        int k = i >> 7, j = i & 127;
        g_B1[i] = (j < 64) ? Wl1[(k << 6) + j] : Wr1[(k << 6) + (j - 64)];
    }
}

// ---------------- input-space mean aggregation: m0 = mean(x[src]) ----------------
__global__ void k_aggx(const float* __restrict__ x) {
    int node = blockIdx.x * 8 + (threadIdx.x >> 5);
    int lane = threadIdx.x & 31;
    if (node >= NN) return;
    int beg = g_off[node], end = g_off[node + 1];
    float inv = 1.0f / (float)max(end - beg, 1);
    float4 a0 = make_float4(0.f, 0.f, 0.f, 0.f);
    float4 a1 = make_float4(0.f, 0.f, 0.f, 0.f);
    int e = beg;
    for (; e + 2 <= end; e += 2) {
        int s0 = g_srcs[e], s1 = g_srcs[e + 1];
        float4 v0 = *(const float4*)&x[(size_t)s0 * 128 + lane * 4];
        float4 v1 = *(const float4*)&x[(size_t)s1 * 128 + lane * 4];
        a0.x += v0.x; a0.y += v0.y; a0.z += v0.z; a0.w += v0.w;
        a1.x += v1.x; a1.y += v1.y; a1.z += v1.z; a1.w += v1.w;
    }
    if (e < end) {
        int s0 = g_srcs[e];
        float4 v0 = *(const float4*)&x[(size_t)s0 * 128 + lane * 4];
        a0.x += v0.x; a0.y += v0.y; a0.z += v0.z; a0.w += v0.w;
    }
    float4 r;
    r.x = (a0.x + a1.x) * inv;
    r.y = (a0.y + a1.y) * inv;
    r.z = (a0.z + a1.z) * inv;
    r.w = (a0.w + a1.w) * inv;
    *(float4*)&g_m0[(size_t)node * 128 + lane * 4] = r;
}

// ---------------- tf32 tensor-core GEMM ----------------
// C[M,128] = A[M,K] @ B[K,128]; PHASE 0: A = concat(m0, x) K=256, epilogue bias+relu -> g_h
//                               PHASE 1: A = g_h K=128, plain store -> g_yz1
// BM=128, BN=128, BK=16; 256 threads = 8 warps (4m x 2n), warp tile 32x64.
template <int PHASE>
__global__ __launch_bounds__(256, 2) void k_gemm(const float* __restrict__ x,
                                                 const float* __restrict__ bias) {
    const int K = (PHASE == 0) ? 256 : 128;
    const float* __restrict__ Bsrc = (PHASE == 0) ? g_B0 : g_B1;

    __shared__ unsigned As[128][20];  // [m][k] tf32, pad->stride 20
    __shared__ unsigned Bs[128][20];  // [n][k] tf32 (transposed fill)

    int tid = threadIdx.x;
    int lane = tid & 31;
    int wid = tid >> 5;
    int warp_m = (wid >> 1) * 32;
    int warp_n = (wid & 1) * 64;
    int m0b = blockIdx.x * 128;

    int aRow = tid >> 1;
    int kLo = (tid & 1) * 8;

    float acc[2][8][4];
#pragma unroll
    for (int mi = 0; mi < 2; mi++)
#pragma unroll
        for (int ni = 0; ni < 8; ni++)
#pragma unroll
            for (int q = 0; q < 4; q++) acc[mi][ni][q] = 0.f;

    int g = lane >> 3, r = lane & 7;

    for (int k0 = 0; k0 < K; k0 += 16) {
        // ---- fill As: A[m][k0+kLo .. +7] (two float4) ----
        const float* __restrict__ A = (PHASE == 0) ? ((k0 < 128) ? g_m0 : x) : g_h;
        int kk = (k0 & 127) + kLo;
        int grow = m0b + aRow;
#pragma unroll
        for (int q = 0; q < 2; q++) {
            float4 av = make_float4(0.f, 0.f, 0.f, 0.f);
            if (grow < NN) av = *(const float4*)&A[(size_t)grow * 128 + kk + q * 4];
            unsigned u0 = f2tf32(av.x), u1 = f2tf32(av.y), u2 = f2tf32(av.z), u3 = f2tf32(av.w);
            *(uint4*)&As[aRow][kLo + q * 4] = make_uint4(u0, u1, u2, u3);
        }
        // ---- fill Bs (transpose): Bs[n][k] = B[k0+k][n] ----
        {
            int bN = tid >> 1;
            int kq = (tid & 1) * 8;
#pragma unroll
            for (int j = 0; j < 8; j++)
                Bs[bN][kq + j] = f2tf32(Bsrc[(size_t)(k0 + kq + j) * 128 + bN]);
        }
        __syncthreads();

#pragma unroll
        for (int ks = 0; ks < 16; ks += 8) {
            unsigned aF[2][4], bF[4][4];
#pragma unroll
            for (int mi = 0; mi < 2; mi++) {
                int row = warp_m + mi * 16 + (g & 1) * 8 + r;
                int col = ks + (g >> 1) * 4;
                unsigned addr = sptr(&As[row][col]);
                LDSM4(aF[mi], addr);
            }
#pragma unroll
            for (int nt = 0; nt < 4; nt++) {
                int row = warp_n + nt * 16 + (g >> 1) * 8 + r;
                int col = ks + (g & 1) * 4;
                unsigned addr = sptr(&Bs[row][col]);
                LDSM4(bF[nt], addr);
            }
#pragma unroll
            for (int mi = 0; mi < 2; mi++)
#pragma unroll
                for (int nt = 0; nt < 4; nt++) {
                    mma_tf32(acc[mi][nt * 2 + 0], aF[mi], bF[nt][0], bF[nt][1]);
                    mma_tf32(acc[mi][nt * 2 + 1], aF[mi], bF[nt][2], bF[nt][3]);
                }
        }
        __syncthreads();
    }

    // ---- epilogue ----
    int rrow = lane >> 2;
    int cquad = (lane & 3) * 2;
#pragma unroll
    for (int mi = 0; mi < 2; mi++) {
        int r0 = m0b + warp_m + mi * 16 + rrow;
#pragma unroll
        for (int ni = 0; ni < 8; ni++) {
            int col = warp_n + ni * 8 + cquad;
            float* c = acc[mi][ni];
            if (PHASE == 0) {
                float b0v = bias[col], b1v = bias[col + 1];
                if (r0 < NN) {
                    float2 v = make_float2(fmaxf(c[0] + b0v, 0.f), fmaxf(c[1] + b1v, 0.f));
                    *(float2*)&g_h[(size_t)r0 * 128 + col] = v;
                }
                if (r0 + 8 < NN) {
                    float2 v = make_float2(fmaxf(c[2] + b0v, 0.f), fmaxf(c[3] + b1v, 0.f));
                    *(float2*)&g_h[(size_t)(r0 + 8) * 128 + col] = v;
                }
            } else {
                if (r0 < NN)
                    *(float2*)&g_yz1[(size_t)r0 * 128 + col] = make_float2(c[0], c[1]);
                if (r0 + 8 < NN)
                    *(float2*)&g_yz1[(size_t)(r0 + 8) * 128 + col] = make_float2(c[2], c[3]);
            }
        }
    }
}

// ---------------- layer-1 aggregate + bias + root ----------------
__global__ void k_agg2(const float* __restrict__ bias, float* __restrict__ out) {
    int node = blockIdx.x * 8 + (threadIdx.x >> 5);
    int lane = threadIdx.x & 31;
    if (node >= NN) return;
    int beg = g_off[node], end = g_off[node + 1];
    float inv = 1.0f / (float)max(end - beg, 1);
    float2 a0 = make_float2(0.f, 0.f), a1 = make_float2(0.f, 0.f);
    int e = beg;
    for (; e + 2 <= end; e += 2) {
        int s0 = g_srcs[e], s1 = g_srcs[e + 1];
        float2 v0 = *(const float2*)&g_yz1[(size_t)s0 * 128 + lane * 2];
        float2 v1 = *(const float2*)&g_yz1[(size_t)s1 * 128 + lane * 2];
        a0.x += v0.x; a0.y += v0.y;
        a1.x += v1.x; a1.y += v1.y;
    }
    if (e < end) {
        int s0 = g_srcs[e];
        float2 v0 = *(const float2*)&g_yz1[(size_t)s0 * 128 + lane * 2];
        a0.x += v0.x; a0.y += v0.y;
    }
    float2 z = *(const float2*)&g_yz1[(size_t)node * 128 + 64 + lane * 2];
    float2 b = *(const float2*)&bias[lane * 2];
    float2 r;
    r.x = fmaf(a0.x + a1.x, inv, b.x + z.x);
    r.y = fmaf(a0.y + a1.y, inv, b.y + z.y);
    *(float2*)&out[(size_t)node * 64 + lane * 2] = r;
}

// ---------------- launch ----------------
extern "C" void kernel_launch(void* const* d_in, const int* in_sizes, int n_in,
                              void* d_out, int out_size) {
    const float* x = (const float*)d_in[0];
    const int* ei = (const int*)d_in[1];          // int32 edge_index [2, NE]
    const float* Wl0 = (const float*)d_in[2];
    const float* bl0 = (const float*)d_in[3];
    const float* Wr0 = (const float*)d_in[4];
    const float* Wl1 = (const float*)d_in[5];
    const float* bl1 = (const float*)d_in[6];
    const float* Wr1 = (const float*)d_in[7];
    float* out = (float*)d_out;

    // CSR build (every launch; graph-replay safe)
    k_zero<<<(NN + 255) / 256, 256>>>();
    k_count<<<(NE + 255) / 256, 256>>>(ei);
    k_scanA<<<NPART, 1024>>>();
    k_scanB<<<1, 32>>>();
    k_scanC<<<NPART, 1024>>>();
    k_scatter<<<(NE + 255) / 256, 256>>>(ei);
    k_pack<<<(256 * 128 + 255) / 256, 256>>>(Wl0, Wr0, Wl1, Wr1);

    int mt = (NN + 127) / 128;  // 782
    // m0 = mean(x[src])
    k_aggx<<<(NN + 7) / 8, 256>>>(x);
    // h = relu(m0 @ Wl0 + x @ Wr0 + b0)   (tf32 tensor cores)
    k_gemm<0><<<mt, 256>>>(x, bl0);
    // yz1 = h @ [W_l1 | W_r1]             (tf32 tensor cores)
    k_gemm<1><<<mt, 256>>>(nullptr, nullptr);
    // out = mean_agg(y1) + b1 + z1
    k_agg2<<<(NN + 7) / 8, 256>>>(bl1, out);
}